// round 16
// baseline (speedup 1.0000x reference)
#include <cuda_runtime.h>
#include <cuda_fp16.h>
#include <cstdint>
#include <math.h>

// Problem constants
// B=4, C=64, H=W=256, N_SPLIT=4 (T=16), RED_FC=32, OUT_NC=32, K=3, FMN1=FMN2=2048
// wsize = 32*64*9 = 18432, wb row = 18464

typedef unsigned long long ull;

// ---------------- scratch (device globals; no runtime allocation) ----------
__device__ float g_u[9*4*65536];               // conv2 tap projections
__device__ float g_adap[4*65536];              // tanh(conv2)
__device__ float g_gram[64*1024];              // pooled grams
__device__ float g_fc1[64*2048];
__device__ float g_fc2[64*2048];
__device__ float g_wb[64*18464];               // dynamic bias (weights go to g_dwh)
__device__ float g_part[9453568];              // split-K partials
__device__ __half g_fh[4*256*256*64];          // feature NHWC fp16
__device__ __half g_w1h[9*64*64];              // rw1 [tap][oc][ic] fp16
__device__ __half g_dwh[64*9*32*64];           // dyn W [r][tap][oc][ic] fp16

// row-major 128B rows with XOR-16B swizzle (bank-conflict-free ldmatrix)
#define SWZ(row, chunk) ((uint32_t)(row)*128u + (((uint32_t)((chunk) ^ ((row) & 7))) * 16u))

// ---------------- helpers ---------------------------------------------------
__device__ __forceinline__ uint32_t smem_u32(const void* p) {
    uint32_t a;
    asm("{ .reg .u64 t; cvta.to.shared.u64 t, %1; cvt.u32.u64 %0, t; }" : "=r"(a) : "l"(p));
    return a;
}
__device__ __forceinline__ void ldm_x4(uint32_t* r, uint32_t addr) {
    asm volatile("ldmatrix.sync.aligned.m8n8.x4.shared.b16 {%0,%1,%2,%3}, [%4];"
        : "=r"(r[0]), "=r"(r[1]), "=r"(r[2]), "=r"(r[3]) : "r"(addr));
}
__device__ __forceinline__ void mma_f16_p(float* d, const uint32_t* a,
                                          uint32_t b0, uint32_t b1) {
    asm volatile(
        "mma.sync.aligned.m16n8k16.row.col.f32.f16.f16.f32 "
        "{%0,%1,%2,%3}, {%4,%5,%6,%7}, {%8,%9}, {%0,%1,%2,%3};"
        : "+f"(d[0]), "+f"(d[1]), "+f"(d[2]), "+f"(d[3])
        : "r"(a[0]), "r"(a[1]), "r"(a[2]), "r"(a[3]), "r"(b0), "r"(b1));
}
__device__ __forceinline__ ull pack2(float lo, float hi) {
    ull d; asm("mov.b64 %0, {%1, %2};" : "=l"(d) : "f"(lo), "f"(hi)); return d;
}
__device__ __forceinline__ void unpack2(ull d, float& lo, float& hi) {
    asm("mov.b64 {%0, %1}, %2;" : "=f"(lo), "=f"(hi) : "l"(d));
}
__device__ __forceinline__ ull fma2(ull a, ull b, ull c) {
    ull d; asm("fma.rn.f32x2 %0, %1, %2, %3;" : "=l"(d) : "l"(a), "l"(b), "l"(c)); return d;
}

// ---------------- NCHW fp32 -> NHWC fp16 (+ feature copy + fused wprep) ----
// grid 4096 + 144: blocks >= 4096 convert rw1 instead.
__global__ __launch_bounds__(256) void tohwc_kernel(const float* __restrict__ feat,
                                                    float* __restrict__ out,
                                                    const float* __restrict__ rw1)
{
    int bx = blockIdx.x;
    int tid = threadIdx.x;
    if (bx >= 4096) {
        int idx = (bx - 4096) * 256 + tid;
        if (idx < 9*64*64) {
            int tap = idx >> 12, rem = idx & 4095;
            int oc = rem >> 6, ic = rem & 63;
            g_w1h[idx] = __float2half_rn(rw1[(oc*64 + ic)*9 + tap]);
        }
        return;
    }
    __shared__ float s[64][65];
    int b = bx >> 10, grp = bx & 1023;
    int pix0 = grp * 64;
#pragma unroll
    for (int i = 0; i < 16; i++) {
        int idx = i * 256 + tid;
        int ic = idx >> 6, px = idx & 63;
        float v = feat[(((size_t)(b*64 + ic)) << 16) + pix0 + px];
        s[ic][px] = v;
        out[(((size_t)(b*96 + ic)) << 16) + pix0 + px] = v;   // fused passthrough
    }
    __syncthreads();
#pragma unroll
    for (int i = 0; i < 16; i++) {
        int idx = i * 256 + tid;
        int px = idx >> 6, ic = idx & 63;
        g_fh[((size_t)b*65536 + pix0 + px) * 64 + ic] = __float2half_rn(s[ic][px]);
    }
}

// ---------------- conv1 via fp16 mma, halo-A, W ping-pong, conv2 proj ------
// grid (8,32,4). block 256 (8 warps), 2 blocks/SM. 1 sync per tap.
// smem: A @0 (43520), W bufs @43520 (2 x 8192 = 16384),
//       bias @59904 (256), w2 @60160 (2304). Total 62464.
__global__ __launch_bounds__(256, 2) void conv1_hmma_kernel(
    const float* __restrict__ rb1, const float* __restrict__ rw2)
{
    extern __shared__ char smem[];
    const uint32_t AS = 0, WB = 43520, BS = 59904, W2 = 60160;
    uint32_t sb = smem_u32(smem);
    int b = blockIdx.z;
    int y0 = blockIdx.y * 8, x0 = blockIdx.x * 32;
    int tid = threadIdx.x, w = tid >> 5, lane = tid & 31;

    if (tid < 64) *(float*)(smem + BS + tid*4) = rb1[tid];
    for (int i = tid; i < 576; i += 256) {
        int tap = i >> 6, ic = i & 63;
        *(float*)(smem + W2 + i*4) = rw2[ic*9 + tap];
    }

    // build swizzled halo A once: 340 rows (10x34 px) x 64 ic fp16
    for (int i = tid; i < 2720; i += 256) {
        int hp = i >> 3, ch8 = i & 7;
        int hy = hp / 34, hx = hp - hy*34;
        int gy = y0 - 1 + hy, gx = x0 - 1 + hx;
        uint4 vh = {0,0,0,0};
        if ((unsigned)gy < 256u && (unsigned)gx < 256u)
            vh = *(const uint4*)(g_fh + ((size_t)(b*256 + gy)*256 + gx)*64 + ch8*8);
        *(uint4*)(smem + AS + SWZ(hp, ch8)) = vh;
    }
    // preload W tap 0 into buf 0
    int wr1 = tid >> 3, wc1 = tid & 7;        // rows 0..31
    int wr2 = wr1 + 32, wc2 = wc1;            // rows 32..63
    {
        *(uint4*)(smem + WB + SWZ(wr1, wc1)) = *(const uint4*)(g_w1h + wr1*64 + wc1*8);
        *(uint4*)(smem + WB + SWZ(wr2, wc2)) = *(const uint4*)(g_w1h + wr2*64 + wc2*8);
    }
    __syncthreads();

    float acc[2][8][4];
#pragma unroll
    for (int mt = 0; mt < 2; mt++)
#pragma unroll
        for (int nt = 0; nt < 8; nt++)
#pragma unroll
            for (int e = 0; e < 4; e++) acc[mt][nt][e] = 0.f;

    int a_row = lane & 15, a_cs = lane >> 4;
    int w_row16 = lane & 15, w_cs16 = lane >> 4;   // 16-row x4 W fragments

    for (int tap = 0; tap < 9; tap++) {
        int dy = tap / 3 - 1, dx = tap % 3 - 1;
        int buf = tap & 1;
        uint32_t wb = WB + buf*8192;

        uint4 ph1, ph2;
        if (tap < 8) {
            size_t gb = (size_t)(tap + 1)*4096;
            ph1 = *(const uint4*)(g_w1h + gb + wr1*64 + wc1*8);
            ph2 = *(const uint4*)(g_w1h + gb + wr2*64 + wc2*8);
        }

        int rb = (w + dy + 1)*34 + dx + 1;
#pragma unroll
        for (int ks = 0; ks < 4; ks++) {
            uint32_t a[2][4];
#pragma unroll
            for (int mt = 0; mt < 2; mt++) {
                int ar = rb + mt*16 + a_row;
                ldm_x4(a[mt], sb + AS + SWZ(ar, ks*2 + a_cs));
            }
#pragma unroll
            for (int p = 0; p < 4; p++) {        // pairs of n8 tiles
                uint32_t wf[4];
                ldm_x4(wf, sb + wb + SWZ(p*16 + w_row16, ks*2 + w_cs16));
                mma_f16_p(acc[0][2*p],     a[0], wf[0], wf[2]);
                mma_f16_p(acc[1][2*p],     a[1], wf[0], wf[2]);
                mma_f16_p(acc[0][2*p + 1], a[0], wf[1], wf[3]);
                mma_f16_p(acc[1][2*p + 1], a[1], wf[1], wf[3]);
            }
        }
        if (tap < 8) {
            uint32_t nb = WB + (buf ^ 1)*8192;
            *(uint4*)(smem + nb + SWZ(wr1, wc1)) = ph1;
            *(uint4*)(smem + nb + SWZ(wr2, wc2)) = ph2;
        }
        __syncthreads();
    }

    // epilogue: bias + leaky relu, then 9 tap-dot projections via f32x2
    const float* bs = (const float*)(smem + BS);
    const float* w2 = (const float*)(smem + W2);
    int g = lane >> 2, c0 = (lane & 3) * 2;
    int y = y0 + w;
#pragma unroll
    for (int mt = 0; mt < 2; mt++) {
#pragma unroll
        for (int half = 0; half < 2; half++) {
            int x = x0 + mt*16 + g + half*8;
            ull part2[9];
#pragma unroll
            for (int t = 0; t < 9; t++) part2[t] = 0ull;
#pragma unroll
            for (int nt = 0; nt < 8; nt++) {
                int oc = nt*8 + c0;
                float v0 = acc[mt][nt][half*2 + 0] + bs[oc];
                float v1 = acc[mt][nt][half*2 + 1] + bs[oc + 1];
                v0 = (v0 >= 0.f) ? v0 : 0.2f * v0;
                v1 = (v1 >= 0.f) ? v1 : 0.2f * v1;
                ull vp = pack2(v0, v1);
#pragma unroll
                for (int t = 0; t < 9; t++)
                    part2[t] = fma2(vp, *(const ull*)(w2 + t*64 + oc), part2[t]);
            }
            float part[9];
#pragma unroll
            for (int t = 0; t < 9; t++) {
                float lo, hi;
                unpack2(part2[t], lo, hi);
                part[t] = lo + hi;
                part[t] += __shfl_xor_sync(0xFFFFFFFFu, part[t], 1);
                part[t] += __shfl_xor_sync(0xFFFFFFFFu, part[t], 2);
            }
            if ((lane & 3) == 0) {
                int pix = y*256 + x;
#pragma unroll
                for (int t = 0; t < 9; t++)
                    g_u[t*262144 + b*65536 + pix] = part[t];
            }
        }
    }
}

// ---------------- conv2 sum: adap = tanh(sum of shifted taps + bias) -------
__global__ __launch_bounds__(256) void conv2_sum_kernel(const float* __restrict__ rb2)
{
    int P = blockIdx.x * 256 + threadIdx.x;
    int b = P >> 16, pix = P & 65535;
    int y = pix >> 8, x = pix & 255;
    float s = 0.f;
#pragma unroll
    for (int t = 0; t < 9; t++) {
        int yy = y + t/3 - 1, xx = x + t%3 - 1;
        if ((unsigned)yy < 256u && (unsigned)xx < 256u)
            s += g_u[t*262144 + b*65536 + yy*256 + xx];
    }
    g_adap[(size_t)b*65536 + pix] = tanhf(s + rb2[0]);
}

// ---------------- adaptive pool per tile -> gram ---------------------------
__global__ void pool_kernel()
{
    __shared__ float win[66][67];
    int r = blockIdx.x;
    int b = r >> 4, t = r & 15;
    int ti = t >> 2, tj = t & 3;
    int tid = threadIdx.x;
    for (int i = tid; i < 66*66; i += 256) {
        int h = i / 66, w = i % 66;
        int gy = ti*64 - 1 + h, gx = tj*64 - 1 + w;
        float v = 0.f;
        if ((unsigned)gy < 256u && (unsigned)gx < 256u)
            v = g_adap[((size_t)b*256 + gy) * 256 + gx];
        win[h][w] = v;
    }
    __syncthreads();
    for (int i = tid; i < 1024; i += 256) {
        int p = i >> 5, q = i & 31;
        int sp = (p*66) >> 5, ep = ((p+1)*66 + 31) >> 5;
        int sq = (q*66) >> 5, eq = ((q+1)*66 + 31) >> 5;
        float s = 0.f;
        for (int h = sp; h < ep; h++)
            for (int w = sq; w < eq; w++)
                s += win[h][w];
        g_gram[r*1024 + i] = s / (float)((ep - sp) * (eq - sq));
    }
}

// ---------------- fp16 split-K FC GEMM (3-stage pipeline) ------------------
// Load for step s+2 issued at step s, stored to smem at s+1, consumed at s+2.
__global__ __launch_bounds__(256) void gemm_hmma_kernel(
    const float* __restrict__ Bm, int K, int N, int KC, int stage)
{
    const float* __restrict__ A = (stage == 0) ? g_gram : (stage == 1) ? g_fc1 : g_fc2;

    __shared__ __half Ah[3][1536];   // [buf][m*24 + k]
    __shared__ __half Bh[3][1536];   // [buf][n*24 + k]

    int n0 = blockIdx.x * 64;
    int k0 = blockIdx.y * KC;
    int tid = threadIdx.x, w = tid >> 5, lane = tid & 31;
    int mt = w >> 1;
    int nh = (w & 1) * 4;            // n8-tile base: 0 or 4

    float acc[4][4];
#pragma unroll
    for (int nt = 0; nt < 4; nt++)
#pragma unroll
        for (int e = 0; e < 4; e++) acc[nt][e] = 0.f;

    uint32_t a_row = lane & 15, a_k16 = (lane >> 4) * 16;
    uint32_t w_row16 = lane & 15, w_k16 = (lane >> 4) * 16;
    uint32_t sAh = smem_u32(Ah);
    uint32_t sBh = smem_u32(Bh);

    int am = tid >> 2, ak = (tid & 3) * 4;
    int bk = tid >> 4, bn = (tid & 15) * 4;
    int col = n0 + bn;
    int nsteps = KC >> 4;

    // step 0: load + store to buf 0
    {
        float4 va = *(const float4*)&A[(size_t)am * K + k0 + ak];
        float4 vb = make_float4(0.f, 0.f, 0.f, 0.f);
        if (col < N) vb = *(const float4*)&Bm[(size_t)(k0 + bk) * N + col];
        const float* vp = (const float*)&va;
        const float* wp = (const float*)&vb;
#pragma unroll
        for (int j = 0; j < 4; j++) {
            Ah[0][am*24 + ak + j] = __float2half_rn(vp[j]);
            Bh[0][(bn + j)*24 + bk] = __float2half_rn(wp[j]);
        }
    }
    // step 1: load into flight regs
    float4 vaP = make_float4(0.f,0.f,0.f,0.f), vbP = make_float4(0.f,0.f,0.f,0.f);
    if (nsteps > 1) {
        vaP = *(const float4*)&A[(size_t)am * K + k0 + 16 + ak];
        if (col < N) vbP = *(const float4*)&Bm[(size_t)(k0 + 16 + bk) * N + col];
    }
    __syncthreads();

    int cur = 0;
    for (int s = 0; s < nsteps; s++) {
        int nxt = (cur == 2) ? 0 : cur + 1;

        // issue load for s+2
        float4 vaN = make_float4(0.f,0.f,0.f,0.f), vbN = make_float4(0.f,0.f,0.f,0.f);
        if (s + 2 < nsteps) {
            int kb = k0 + (s + 2)*16;
            vaN = *(const float4*)&A[(size_t)am * K + kb + ak];
            if (col < N) vbN = *(const float4*)&Bm[(size_t)(kb + bk) * N + col];
        }
        // store load(s+1) into buf nxt
        if (s + 1 < nsteps) {
            const float* vp = (const float*)&vaP;
            const float* wp = (const float*)&vbP;
#pragma unroll
            for (int j = 0; j < 4; j++) {
                Ah[nxt][am*24 + ak + j] = __float2half_rn(vp[j]);
                Bh[nxt][(bn + j)*24 + bk] = __float2half_rn(wp[j]);
            }
        }

        uint32_t cb = (uint32_t)cur * 3072;
        uint32_t a[4];
        ldm_x4(a, sAh + cb + (uint32_t)(mt*16 + a_row)*48 + a_k16);
#pragma unroll
        for (int p = 0; p < 2; p++) {           // pairs of n8 tiles
            uint32_t wf[4];
            uint32_t base_row = (nh + 2*p)*8 + w_row16;
            ldm_x4(wf, sBh + cb + base_row*48 + w_k16);
            mma_f16_p(acc[2*p],     a, wf[0], wf[2]);
            mma_f16_p(acc[2*p + 1], a, wf[1], wf[3]);
        }

        vaP = vaN; vbP = vbN;
        __syncthreads();
        cur = nxt;
    }

    int s = blockIdx.y;
    int g = lane >> 2, c0 = (lane & 3) * 2;
#pragma unroll
    for (int nt = 0; nt < 4; nt++) {
#pragma unroll
        for (int half = 0; half < 2; half++) {
            int row = mt*16 + g + half*8;
            int ocol = n0 + (nh + nt)*8 + c0;
            if (ocol < N) {
                float* p = &g_part[((size_t)(s*64 + row)) * N + ocol];
                p[0] = acc[nt][half*2 + 0];
                p[1] = acc[nt][half*2 + 1];
            }
        }
    }
}

// ---------------- split-K reduce + bias + activation (+ fused dyn W prep) --
// stage 2 writes dyn weights directly to g_dwh (fp16, [r][tap][oc*64+ic])
// and biases to g_wb; stages 0/1 unchanged.
__global__ void gemm_reduce_kernel(const float* __restrict__ bias,
                                   int N, int nsplit, int relu, int stage)
{
    float* out = (stage == 0) ? g_fc1 : (stage == 1) ? g_fc2 : g_wb;
    int nv = N >> 2;
    int idx = blockIdx.x * 256 + threadIdx.x;
    if (idx >= 64 * nv) return;
    int m = idx / nv, f = idx - m * nv;
    float4 s = make_float4(0.f, 0.f, 0.f, 0.f);
    for (int sp = 0; sp < nsplit; sp++) {
        const float4* p = (const float4*)&g_part[(size_t)(sp*64 + m) * N];
        float4 v = p[f];
        s.x += v.x; s.y += v.y; s.z += v.z; s.w += v.w;
    }
    float4 bv = ((const float4*)bias)[f];
    s.x += bv.x; s.y += bv.y; s.z += bv.z; s.w += bv.w;
    if (relu) {
        s.x = fmaxf(s.x, 0.f); s.y = fmaxf(s.y, 0.f);
        s.z = fmaxf(s.z, 0.f); s.w = fmaxf(s.w, 0.f);
    }
    if (stage != 2) {
        ((float4*)out)[(size_t)m * nv + f] = s;
    } else {
        const float* sv = (const float*)&s;
#pragma unroll
        for (int j = 0; j < 4; j++) {
            int c = f*4 + j;
            if (c < 18432) {
                int rem = c / 9, tap = c - rem*9;
                g_dwh[((size_t)(m*9 + tap))*2048 + rem] = __float2half_rn(sv[j]);
            } else {
                g_wb[(size_t)m * 18464 + c] = sv[j];
            }
        }
    }
}

// ---------------- dynamic per-tile conv via fp16 mma, halo-A, W ping-pong --
// grid (2,8,64). block 256, 2 blocks/SM.
// smem: A @0 (43520), W bufs @43520 (2 x 4096 = 8192), bias @51712 (128).
// Total 51840.
__global__ __launch_bounds__(256, 2) void dynconv_hmma_kernel(float* __restrict__ out)
{
    extern __shared__ char smem[];
    const uint32_t AS = 0, WB = 43520, BS = 51712;
    uint32_t sb = smem_u32(smem);
    int r = blockIdx.z;
    int b = r >> 4, t = r & 15;
    int ti = t >> 2, tj = t & 3;
    int y0 = ti*64 + blockIdx.y * 8;
    int x0 = tj*64 + blockIdx.x * 32;
    int tid = threadIdx.x, w = tid >> 5, lane = tid & 31;

    if (tid < 32) *(float*)(smem + BS + tid*4) = g_wb[(size_t)r*18464 + 18432 + tid];

    // build swizzled halo A once (fp16)
    for (int i = tid; i < 2720; i += 256) {
        int hp = i >> 3, ch8 = i & 7;
        int hy = hp / 34, hx = hp - hy*34;
        int gy = y0 - 1 + hy, gx = x0 - 1 + hx;
        uint4 vh = {0,0,0,0};
        if ((unsigned)gy < 256u && (unsigned)gx < 256u)
            vh = *(const uint4*)(g_fh + ((size_t)(b*256 + gy)*256 + gx)*64 + ch8*8);
        *(uint4*)(smem + AS + SWZ(hp, ch8)) = vh;
    }
    // preload W tap 0 into buf 0
    const __half* dwh = g_dwh + (size_t)r*9*2048;
    int wr = tid >> 3, wc = tid & 7;
    *(uint4*)(smem + WB + SWZ(wr, wc)) = *(const uint4*)(dwh + wr*64 + wc*8);
    __syncthreads();

    float acc[2][4][4];
#pragma unroll
    for (int mt = 0; mt < 2; mt++)
#pragma unroll
        for (int nt = 0; nt < 4; nt++)
#pragma unroll
            for (int e = 0; e < 4; e++) acc[mt][nt][e] = 0.f;

    int a_row = lane & 15, a_cs = lane >> 4;
    int w_row16 = lane & 15, w_cs16 = lane >> 4;

    for (int tap = 0; tap < 9; tap++) {
        int dy = tap / 3 - 1, dx = tap % 3 - 1;
        int buf = tap & 1;
        uint32_t wb = WB + buf*4096;

        uint4 ph;
        if (tap < 8)
            ph = *(const uint4*)(dwh + (tap + 1)*2048 + wr*64 + wc*8);

        int rb = (w + dy + 1)*34 + dx + 1;
#pragma unroll
        for (int ks = 0; ks < 4; ks++) {
            uint32_t a[2][4];
#pragma unroll
            for (int mt = 0; mt < 2; mt++) {
                int ar = rb + mt*16 + a_row;
                ldm_x4(a[mt], sb + AS + SWZ(ar, ks*2 + a_cs));
            }
#pragma unroll
            for (int p = 0; p < 2; p++) {        // pairs of n8 tiles
                uint32_t wf[4];
                ldm_x4(wf, sb + wb + SWZ(p*16 + w_row16, ks*2 + w_cs16));
                mma_f16_p(acc[0][2*p],     a[0], wf[0], wf[2]);
                mma_f16_p(acc[1][2*p],     a[1], wf[0], wf[2]);
                mma_f16_p(acc[0][2*p + 1], a[0], wf[1], wf[3]);
                mma_f16_p(acc[1][2*p + 1], a[1], wf[1], wf[3]);
            }
        }
        if (tap < 8) {
            uint32_t nb = WB + (buf ^ 1)*4096;
            *(uint4*)(smem + nb + SWZ(wr, wc)) = ph;
        }
        __syncthreads();
    }

    const float* bsm = (const float*)(smem + BS);
    int g = lane >> 2, c0 = (lane & 3) * 2;
    int y = y0 + w;
#pragma unroll
    for (int mt = 0; mt < 2; mt++) {
#pragma unroll
        for (int half = 0; half < 2; half++) {
            int x = x0 + mt*16 + g + half*8;
            int pix = y*256 + x;
#pragma unroll
            for (int nt = 0; nt < 4; nt++) {
                int oc = nt*8 + c0;
                float v0 = acc[mt][nt][half*2 + 0] + bsm[oc];
                float v1 = acc[mt][nt][half*2 + 1] + bsm[oc + 1];
                out[(((size_t)(b*96 + 64 + oc)) << 16) + pix] = v0;
                out[(((size_t)(b*96 + 64 + oc + 1)) << 16) + pix] = v1;
            }
        }
    }
}

// ---------------- launch ---------------------------------------------------
extern "C" void kernel_launch(void* const* d_in, const int* in_sizes, int n_in,
                              void* d_out, int out_size)
{
    const float* feature = (const float*)d_in[0];
    const float* rw1 = (const float*)d_in[1];
    const float* rb1 = (const float*)d_in[2];
    const float* rw2 = (const float*)d_in[3];
    const float* rb2 = (const float*)d_in[4];
    const float* fw1 = (const float*)d_in[5];
    const float* fb1 = (const float*)d_in[6];
    const float* fw2 = (const float*)d_in[7];
    const float* fb2 = (const float*)d_in[8];
    const float* fw3 = (const float*)d_in[9];
    const float* fb3 = (const float*)d_in[10];
    float* out = (float*)d_out;

    const int CONV1_SMEM = 62464;
    const int DYN_SMEM = 51840;
    cudaFuncSetAttribute(conv1_hmma_kernel,
                         cudaFuncAttributeMaxDynamicSharedMemorySize, CONV1_SMEM);
    cudaFuncSetAttribute(dynconv_hmma_kernel,
                         cudaFuncAttributeMaxDynamicSharedMemorySize, DYN_SMEM);

    tohwc_kernel<<<4240, 256>>>(feature, out, rw1);     // + fused wprep
    conv1_hmma_kernel<<<dim3(8, 32, 4), 256, CONV1_SMEM>>>(rb1, rw2);
    conv2_sum_kernel<<<1024, 256>>>(rb2);
    pool_kernel<<<64, 256>>>();

    // FC1: 64x1024 @ 1024x2048, split-K 16 (fp16 3-stage)
    gemm_hmma_kernel<<<dim3(32, 16), 256>>>(fw1, 1024, 2048, 64, 0);
    gemm_reduce_kernel<<<(64*512 + 255)/256, 256>>>(fb1, 2048, 16, 1, 0);
    // FC2: 64x2048 @ 2048x2048, split-K 16 (fp16 3-stage)
    gemm_hmma_kernel<<<dim3(32, 16), 256>>>(fw2, 2048, 2048, 128, 1);
    gemm_reduce_kernel<<<(64*512 + 255)/256, 256>>>(fb2, 2048, 16, 1, 1);
    // FC3: 64x2048 @ 2048x18464, split-K 2 (fp16 3-stage) + fused dyn W prep
    gemm_hmma_kernel<<<dim3(289, 2), 256>>>(fw3, 2048, 18464, 1024, 2);
    gemm_reduce_kernel<<<(64*4616 + 255)/256, 256>>>(fb3, 18464, 2, 0, 2);

    dynconv_hmma_kernel<<<dim3(2, 8, 64), 256, DYN_SMEM>>>(out);
}

// round 17
// speedup vs baseline: 1.0370x; 1.0370x over previous
#include <cuda_runtime.h>
#include <cuda_fp16.h>
#include <cstdint>
#include <math.h>

// Problem constants
// B=4, C=64, H=W=256, N_SPLIT=4 (T=16), RED_FC=32, OUT_NC=32, K=3, FMN1=FMN2=2048
// wsize = 32*64*9 = 18432, wb row = 18464

typedef unsigned long long ull;

// ---------------- scratch (device globals; no runtime allocation) ----------
__device__ float g_u[9*4*65536];               // conv2 tap projections
__device__ float g_gram[64*1024];              // pooled grams
__device__ float g_fc1[64*2048];
__device__ float g_fc2[64*2048];
__device__ float g_wb[64*18464];               // dynamic bias (weights go to g_dwh)
__device__ float g_part[9453568];              // split-K partials
__device__ __half g_fh[4*256*256*64];          // feature NHWC fp16
__device__ __half g_w1h[9*64*64];              // rw1 [tap][oc][ic] fp16
__device__ __half g_dwh[64*9*32*64];           // dyn W [r][tap][oc][ic] fp16

// row-major 128B rows with XOR-16B swizzle (bank-conflict-free ldmatrix)
#define SWZ(row, chunk) ((uint32_t)(row)*128u + (((uint32_t)((chunk) ^ ((row) & 7))) * 16u))

// ---------------- helpers ---------------------------------------------------
__device__ __forceinline__ uint32_t smem_u32(const void* p) {
    uint32_t a;
    asm("{ .reg .u64 t; cvta.to.shared.u64 t, %1; cvt.u32.u64 %0, t; }" : "=r"(a) : "l"(p));
    return a;
}
__device__ __forceinline__ void ldm_x4(uint32_t* r, uint32_t addr) {
    asm volatile("ldmatrix.sync.aligned.m8n8.x4.shared.b16 {%0,%1,%2,%3}, [%4];"
        : "=r"(r[0]), "=r"(r[1]), "=r"(r[2]), "=r"(r[3]) : "r"(addr));
}
__device__ __forceinline__ void mma_f16_p(float* d, const uint32_t* a,
                                          uint32_t b0, uint32_t b1) {
    asm volatile(
        "mma.sync.aligned.m16n8k16.row.col.f32.f16.f16.f32 "
        "{%0,%1,%2,%3}, {%4,%5,%6,%7}, {%8,%9}, {%0,%1,%2,%3};"
        : "+f"(d[0]), "+f"(d[1]), "+f"(d[2]), "+f"(d[3])
        : "r"(a[0]), "r"(a[1]), "r"(a[2]), "r"(a[3]), "r"(b0), "r"(b1));
}
__device__ __forceinline__ ull pack2(float lo, float hi) {
    ull d; asm("mov.b64 %0, {%1, %2};" : "=l"(d) : "f"(lo), "f"(hi)); return d;
}
__device__ __forceinline__ void unpack2(ull d, float& lo, float& hi) {
    asm("mov.b64 {%0, %1}, %2;" : "=f"(lo), "=f"(hi) : "l"(d));
}
__device__ __forceinline__ ull fma2(ull a, ull b, ull c) {
    ull d; asm("fma.rn.f32x2 %0, %1, %2, %3;" : "=l"(d) : "l"(a), "l"(b), "l"(c)); return d;
}

// ---------------- NCHW fp32 -> NHWC fp16 (+ feature copy + fused wprep) ----
// grid 4096 + 144: blocks >= 4096 convert rw1 instead.
__global__ __launch_bounds__(256) void tohwc_kernel(const float* __restrict__ feat,
                                                    float* __restrict__ out,
                                                    const float* __restrict__ rw1)
{
    int bx = blockIdx.x;
    int tid = threadIdx.x;
    if (bx >= 4096) {
        int idx = (bx - 4096) * 256 + tid;
        if (idx < 9*64*64) {
            int tap = idx >> 12, rem = idx & 4095;
            int oc = rem >> 6, ic = rem & 63;
            g_w1h[idx] = __float2half_rn(rw1[(oc*64 + ic)*9 + tap]);
        }
        return;
    }
    __shared__ float s[64][65];
    int b = bx >> 10, grp = bx & 1023;
    int pix0 = grp * 64;
#pragma unroll
    for (int i = 0; i < 16; i++) {
        int idx = i * 256 + tid;
        int ic = idx >> 6, px = idx & 63;
        float v = feat[(((size_t)(b*64 + ic)) << 16) + pix0 + px];
        s[ic][px] = v;
        out[(((size_t)(b*96 + ic)) << 16) + pix0 + px] = v;   // fused passthrough
    }
    __syncthreads();
#pragma unroll
    for (int i = 0; i < 16; i++) {
        int idx = i * 256 + tid;
        int px = idx >> 6, ic = idx & 63;
        g_fh[((size_t)b*65536 + pix0 + px) * 64 + ic] = __float2half_rn(s[ic][px]);
    }
}

// ---------------- conv1 via fp16 mma, halo-A, W ping-pong, conv2 proj ------
// grid (8,32,4). block 256 (8 warps), 2 blocks/SM. 1 sync per tap.
// smem: A @0 (43520), W bufs @43520 (2 x 8192 = 16384),
//       bias @59904 (256), w2 @60160 (2304). Total 62464.
__global__ __launch_bounds__(256, 2) void conv1_hmma_kernel(
    const float* __restrict__ rb1, const float* __restrict__ rw2)
{
    extern __shared__ char smem[];
    const uint32_t AS = 0, WB = 43520, BS = 59904, W2 = 60160;
    uint32_t sb = smem_u32(smem);
    int b = blockIdx.z;
    int y0 = blockIdx.y * 8, x0 = blockIdx.x * 32;
    int tid = threadIdx.x, w = tid >> 5, lane = tid & 31;

    if (tid < 64) *(float*)(smem + BS + tid*4) = rb1[tid];
    for (int i = tid; i < 576; i += 256) {
        int tap = i >> 6, ic = i & 63;
        *(float*)(smem + W2 + i*4) = rw2[ic*9 + tap];
    }

    // build swizzled halo A once: 340 rows (10x34 px) x 64 ic fp16
    for (int i = tid; i < 2720; i += 256) {
        int hp = i >> 3, ch8 = i & 7;
        int hy = hp / 34, hx = hp - hy*34;
        int gy = y0 - 1 + hy, gx = x0 - 1 + hx;
        uint4 vh = {0,0,0,0};
        if ((unsigned)gy < 256u && (unsigned)gx < 256u)
            vh = *(const uint4*)(g_fh + ((size_t)(b*256 + gy)*256 + gx)*64 + ch8*8);
        *(uint4*)(smem + AS + SWZ(hp, ch8)) = vh;
    }
    // preload W tap 0 into buf 0
    int wr1 = tid >> 3, wc1 = tid & 7;        // rows 0..31
    int wr2 = wr1 + 32, wc2 = wc1;            // rows 32..63
    {
        *(uint4*)(smem + WB + SWZ(wr1, wc1)) = *(const uint4*)(g_w1h + wr1*64 + wc1*8);
        *(uint4*)(smem + WB + SWZ(wr2, wc2)) = *(const uint4*)(g_w1h + wr2*64 + wc2*8);
    }
    __syncthreads();

    float acc[2][8][4];
#pragma unroll
    for (int mt = 0; mt < 2; mt++)
#pragma unroll
        for (int nt = 0; nt < 8; nt++)
#pragma unroll
            for (int e = 0; e < 4; e++) acc[mt][nt][e] = 0.f;

    int a_row = lane & 15, a_cs = lane >> 4;
    int w_row16 = lane & 15, w_cs16 = lane >> 4;   // 16-row x4 W fragments

    for (int tap = 0; tap < 9; tap++) {
        int dy = tap / 3 - 1, dx = tap % 3 - 1;
        int buf = tap & 1;
        uint32_t wb = WB + buf*8192;

        uint4 ph1, ph2;
        if (tap < 8) {
            size_t gb = (size_t)(tap + 1)*4096;
            ph1 = *(const uint4*)(g_w1h + gb + wr1*64 + wc1*8);
            ph2 = *(const uint4*)(g_w1h + gb + wr2*64 + wc2*8);
        }

        int rb = (w + dy + 1)*34 + dx + 1;
#pragma unroll
        for (int ks = 0; ks < 4; ks++) {
            uint32_t a[2][4];
#pragma unroll
            for (int mt = 0; mt < 2; mt++) {
                int ar = rb + mt*16 + a_row;
                ldm_x4(a[mt], sb + AS + SWZ(ar, ks*2 + a_cs));
            }
#pragma unroll
            for (int p = 0; p < 4; p++) {        // pairs of n8 tiles
                uint32_t wf[4];
                ldm_x4(wf, sb + wb + SWZ(p*16 + w_row16, ks*2 + w_cs16));
                mma_f16_p(acc[0][2*p],     a[0], wf[0], wf[2]);
                mma_f16_p(acc[1][2*p],     a[1], wf[0], wf[2]);
                mma_f16_p(acc[0][2*p + 1], a[0], wf[1], wf[3]);
                mma_f16_p(acc[1][2*p + 1], a[1], wf[1], wf[3]);
            }
        }
        if (tap < 8) {
            uint32_t nb = WB + (buf ^ 1)*8192;
            *(uint4*)(smem + nb + SWZ(wr1, wc1)) = ph1;
            *(uint4*)(smem + nb + SWZ(wr2, wc2)) = ph2;
        }
        __syncthreads();
    }

    // epilogue: bias + leaky relu, then 9 tap-dot projections via f32x2
    const float* bs = (const float*)(smem + BS);
    const float* w2 = (const float*)(smem + W2);
    int g = lane >> 2, c0 = (lane & 3) * 2;
    int y = y0 + w;
#pragma unroll
    for (int mt = 0; mt < 2; mt++) {
#pragma unroll
        for (int half = 0; half < 2; half++) {
            int x = x0 + mt*16 + g + half*8;
            ull part2[9];
#pragma unroll
            for (int t = 0; t < 9; t++) part2[t] = 0ull;
#pragma unroll
            for (int nt = 0; nt < 8; nt++) {
                int oc = nt*8 + c0;
                float v0 = acc[mt][nt][half*2 + 0] + bs[oc];
                float v1 = acc[mt][nt][half*2 + 1] + bs[oc + 1];
                v0 = (v0 >= 0.f) ? v0 : 0.2f * v0;
                v1 = (v1 >= 0.f) ? v1 : 0.2f * v1;
                ull vp = pack2(v0, v1);
#pragma unroll
                for (int t = 0; t < 9; t++)
                    part2[t] = fma2(vp, *(const ull*)(w2 + t*64 + oc), part2[t]);
            }
            float part[9];
#pragma unroll
            for (int t = 0; t < 9; t++) {
                float lo, hi;
                unpack2(part2[t], lo, hi);
                part[t] = lo + hi;
                part[t] += __shfl_xor_sync(0xFFFFFFFFu, part[t], 1);
                part[t] += __shfl_xor_sync(0xFFFFFFFFu, part[t], 2);
            }
            if ((lane & 3) == 0) {
                int pix = y*256 + x;
#pragma unroll
                for (int t = 0; t < 9; t++)
                    g_u[t*262144 + b*65536 + pix] = part[t];
            }
        }
    }
}

// ---------------- fused conv2+pool: gram from g_u directly -----------------
// grid 256, block 256: thread = one gram output (r = b*16+t, cell p,q).
// adap(gy,gx) = tanh(sum_t g_u[t][gy+dy][gx+dx] + b2), recomputed per use
// (identical arithmetic order to the old conv2_sum + pool chain).
__global__ __launch_bounds__(256) void pool_fused_kernel(const float* __restrict__ rb2)
{
    int idx = blockIdx.x * 256 + threadIdx.x;    // 0..65535
    int r = idx >> 10;                           // b*16 + t
    int cell = idx & 1023;
    int p = cell >> 5, q = cell & 31;
    int b = r >> 4, t = r & 15;
    int ti = t >> 2, tj = t & 3;
    float b2 = rb2[0];

    int sp = (p*66) >> 5, ep = ((p+1)*66 + 31) >> 5;
    int sq = (q*66) >> 5, eq = ((q+1)*66 + 31) >> 5;

    const float* ub = g_u + b*65536;
    float s = 0.f;
    for (int h = sp; h < ep; h++) {
        int gy = ti*64 - 1 + h;
        for (int w = sq; w < eq; w++) {
            int gx = tj*64 - 1 + w;
            float v = 0.f;
            if ((unsigned)gy < 256u && (unsigned)gx < 256u) {
                float a = 0.f;
#pragma unroll
                for (int tp = 0; tp < 9; tp++) {
                    int yy = gy + tp/3 - 1, xx = gx + tp%3 - 1;
                    if ((unsigned)yy < 256u && (unsigned)xx < 256u)
                        a += ub[tp*262144 + yy*256 + xx];
                }
                v = tanhf(a + b2);
            }
            s += v;
        }
    }
    g_gram[r*1024 + cell] = s / (float)((ep - sp) * (eq - sq));
}

// ---------------- fp16 split-K FC GEMM (3-stage pipeline) ------------------
__global__ __launch_bounds__(256) void gemm_hmma_kernel(
    const float* __restrict__ Bm, int K, int N, int KC, int stage)
{
    const float* __restrict__ A = (stage == 0) ? g_gram : (stage == 1) ? g_fc1 : g_fc2;

    __shared__ __half Ah[3][1536];   // [buf][m*24 + k]
    __shared__ __half Bh[3][1536];   // [buf][n*24 + k]

    int n0 = blockIdx.x * 64;
    int k0 = blockIdx.y * KC;
    int tid = threadIdx.x, w = tid >> 5, lane = tid & 31;
    int mt = w >> 1;
    int nh = (w & 1) * 4;            // n8-tile base: 0 or 4

    float acc[4][4];
#pragma unroll
    for (int nt = 0; nt < 4; nt++)
#pragma unroll
        for (int e = 0; e < 4; e++) acc[nt][e] = 0.f;

    uint32_t a_row = lane & 15, a_k16 = (lane >> 4) * 16;
    uint32_t w_row16 = lane & 15, w_k16 = (lane >> 4) * 16;
    uint32_t sAh = smem_u32(Ah);
    uint32_t sBh = smem_u32(Bh);

    int am = tid >> 2, ak = (tid & 3) * 4;
    int bk = tid >> 4, bn = (tid & 15) * 4;
    int col = n0 + bn;
    int nsteps = KC >> 4;

    // step 0: load + store to buf 0
    {
        float4 va = *(const float4*)&A[(size_t)am * K + k0 + ak];
        float4 vb = make_float4(0.f, 0.f, 0.f, 0.f);
        if (col < N) vb = *(const float4*)&Bm[(size_t)(k0 + bk) * N + col];
        const float* vp = (const float*)&va;
        const float* wp = (const float*)&vb;
#pragma unroll
        for (int j = 0; j < 4; j++) {
            Ah[0][am*24 + ak + j] = __float2half_rn(vp[j]);
            Bh[0][(bn + j)*24 + bk] = __float2half_rn(wp[j]);
        }
    }
    // step 1: load into flight regs
    float4 vaP = make_float4(0.f,0.f,0.f,0.f), vbP = make_float4(0.f,0.f,0.f,0.f);
    if (nsteps > 1) {
        vaP = *(const float4*)&A[(size_t)am * K + k0 + 16 + ak];
        if (col < N) vbP = *(const float4*)&Bm[(size_t)(k0 + 16 + bk) * N + col];
    }
    __syncthreads();

    int cur = 0;
    for (int s = 0; s < nsteps; s++) {
        int nxt = (cur == 2) ? 0 : cur + 1;

        float4 vaN = make_float4(0.f,0.f,0.f,0.f), vbN = make_float4(0.f,0.f,0.f,0.f);
        if (s + 2 < nsteps) {
            int kb = k0 + (s + 2)*16;
            vaN = *(const float4*)&A[(size_t)am * K + kb + ak];
            if (col < N) vbN = *(const float4*)&Bm[(size_t)(kb + bk) * N + col];
        }
        if (s + 1 < nsteps) {
            const float* vp = (const float*)&vaP;
            const float* wp = (const float*)&vbP;
#pragma unroll
            for (int j = 0; j < 4; j++) {
                Ah[nxt][am*24 + ak + j] = __float2half_rn(vp[j]);
                Bh[nxt][(bn + j)*24 + bk] = __float2half_rn(wp[j]);
            }
        }

        uint32_t cb = (uint32_t)cur * 3072;
        uint32_t a[4];
        ldm_x4(a, sAh + cb + (uint32_t)(mt*16 + a_row)*48 + a_k16);
#pragma unroll
        for (int p = 0; p < 2; p++) {           // pairs of n8 tiles
            uint32_t wf[4];
            uint32_t base_row = (nh + 2*p)*8 + w_row16;
            ldm_x4(wf, sBh + cb + base_row*48 + w_k16);
            mma_f16_p(acc[2*p],     a, wf[0], wf[2]);
            mma_f16_p(acc[2*p + 1], a, wf[1], wf[3]);
        }

        vaP = vaN; vbP = vbN;
        __syncthreads();
        cur = nxt;
    }

    int s = blockIdx.y;
    int g = lane >> 2, c0 = (lane & 3) * 2;
#pragma unroll
    for (int nt = 0; nt < 4; nt++) {
#pragma unroll
        for (int half = 0; half < 2; half++) {
            int row = mt*16 + g + half*8;
            int ocol = n0 + (nh + nt)*8 + c0;
            if (ocol < N) {
                float* p = &g_part[((size_t)(s*64 + row)) * N + ocol];
                p[0] = acc[nt][half*2 + 0];
                p[1] = acc[nt][half*2 + 1];
            }
        }
    }
}

// ---------------- split-K reduce + bias + activation (+ fused dyn W prep) --
__global__ void gemm_reduce_kernel(const float* __restrict__ bias,
                                   int N, int nsplit, int relu, int stage)
{
    float* out = (stage == 0) ? g_fc1 : (stage == 1) ? g_fc2 : g_wb;
    int nv = N >> 2;
    int idx = blockIdx.x * 256 + threadIdx.x;
    if (idx >= 64 * nv) return;
    int m = idx / nv, f = idx - m * nv;
    float4 s = make_float4(0.f, 0.f, 0.f, 0.f);
    for (int sp = 0; sp < nsplit; sp++) {
        const float4* p = (const float4*)&g_part[(size_t)(sp*64 + m) * N];
        float4 v = p[f];
        s.x += v.x; s.y += v.y; s.z += v.z; s.w += v.w;
    }
    float4 bv = ((const float4*)bias)[f];
    s.x += bv.x; s.y += bv.y; s.z += bv.z; s.w += bv.w;
    if (relu) {
        s.x = fmaxf(s.x, 0.f); s.y = fmaxf(s.y, 0.f);
        s.z = fmaxf(s.z, 0.f); s.w = fmaxf(s.w, 0.f);
    }
    if (stage != 2) {
        ((float4*)out)[(size_t)m * nv + f] = s;
    } else {
        const float* sv = (const float*)&s;
#pragma unroll
        for (int j = 0; j < 4; j++) {
            int c = f*4 + j;
            if (c < 18432) {
                int rem = c / 9, tap = c - rem*9;
                g_dwh[((size_t)(m*9 + tap))*2048 + rem] = __float2half_rn(sv[j]);
            } else {
                g_wb[(size_t)m * 18464 + c] = sv[j];
            }
        }
    }
}

// ---------------- dynamic per-tile conv via fp16 mma, halo-A, W ping-pong --
// grid (2,8,64). block 256, 3 blocks/SM.
// smem: A @0 (43520), W bufs @43520 (2 x 4096 = 8192), bias @51712 (128).
// Total 51840.
__global__ __launch_bounds__(256, 3) void dynconv_hmma_kernel(float* __restrict__ out)
{
    extern __shared__ char smem[];
    const uint32_t AS = 0, WB = 43520, BS = 51712;
    uint32_t sb = smem_u32(smem);
    int r = blockIdx.z;
    int b = r >> 4, t = r & 15;
    int ti = t >> 2, tj = t & 3;
    int y0 = ti*64 + blockIdx.y * 8;
    int x0 = tj*64 + blockIdx.x * 32;
    int tid = threadIdx.x, w = tid >> 5, lane = tid & 31;

    if (tid < 32) *(float*)(smem + BS + tid*4) = g_wb[(size_t)r*18464 + 18432 + tid];

    // build swizzled halo A once (fp16)
    for (int i = tid; i < 2720; i += 256) {
        int hp = i >> 3, ch8 = i & 7;
        int hy = hp / 34, hx = hp - hy*34;
        int gy = y0 - 1 + hy, gx = x0 - 1 + hx;
        uint4 vh = {0,0,0,0};
        if ((unsigned)gy < 256u && (unsigned)gx < 256u)
            vh = *(const uint4*)(g_fh + ((size_t)(b*256 + gy)*256 + gx)*64 + ch8*8);
        *(uint4*)(smem + AS + SWZ(hp, ch8)) = vh;
    }
    // preload W tap 0 into buf 0
    const __half* dwh = g_dwh + (size_t)r*9*2048;
    int wr = tid >> 3, wc = tid & 7;
    *(uint4*)(smem + WB + SWZ(wr, wc)) = *(const uint4*)(dwh + wr*64 + wc*8);
    __syncthreads();

    float acc[2][4][4];
#pragma unroll
    for (int mt = 0; mt < 2; mt++)
#pragma unroll
        for (int nt = 0; nt < 4; nt++)
#pragma unroll
            for (int e = 0; e < 4; e++) acc[mt][nt][e] = 0.f;

    int a_row = lane & 15, a_cs = lane >> 4;
    int w_row16 = lane & 15, w_cs16 = lane >> 4;

    for (int tap = 0; tap < 9; tap++) {
        int dy = tap / 3 - 1, dx = tap % 3 - 1;
        int buf = tap & 1;
        uint32_t wb = WB + buf*4096;

        uint4 ph;
        if (tap < 8)
            ph = *(const uint4*)(dwh + (tap + 1)*2048 + wr*64 + wc*8);

        int rb = (w + dy + 1)*34 + dx + 1;
#pragma unroll
        for (int ks = 0; ks < 4; ks++) {
            uint32_t a[2][4];
#pragma unroll
            for (int mt = 0; mt < 2; mt++) {
                int ar = rb + mt*16 + a_row;
                ldm_x4(a[mt], sb + AS + SWZ(ar, ks*2 + a_cs));
            }
#pragma unroll
            for (int p = 0; p < 2; p++) {        // pairs of n8 tiles
                uint32_t wf[4];
                ldm_x4(wf, sb + wb + SWZ(p*16 + w_row16, ks*2 + w_cs16));
                mma_f16_p(acc[0][2*p],     a[0], wf[0], wf[2]);
                mma_f16_p(acc[1][2*p],     a[1], wf[0], wf[2]);
                mma_f16_p(acc[0][2*p + 1], a[0], wf[1], wf[3]);
                mma_f16_p(acc[1][2*p + 1], a[1], wf[1], wf[3]);
            }
        }
        if (tap < 8) {
            uint32_t nb = WB + (buf ^ 1)*4096;
            *(uint4*)(smem + nb + SWZ(wr, wc)) = ph;
        }
        __syncthreads();
    }

    const float* bsm = (const float*)(smem + BS);
    int g = lane >> 2, c0 = (lane & 3) * 2;
    int y = y0 + w;
#pragma unroll
    for (int mt = 0; mt < 2; mt++) {
#pragma unroll
        for (int half = 0; half < 2; half++) {
            int x = x0 + mt*16 + g + half*8;
            int pix = y*256 + x;
#pragma unroll
            for (int nt = 0; nt < 4; nt++) {
                int oc = nt*8 + c0;
                float v0 = acc[mt][nt][half*2 + 0] + bsm[oc];
                float v1 = acc[mt][nt][half*2 + 1] + bsm[oc + 1];
                out[(((size_t)(b*96 + 64 + oc)) << 16) + pix] = v0;
                out[(((size_t)(b*96 + 64 + oc + 1)) << 16) + pix] = v1;
            }
        }
    }
}

// ---------------- launch ---------------------------------------------------
extern "C" void kernel_launch(void* const* d_in, const int* in_sizes, int n_in,
                              void* d_out, int out_size)
{
    const float* feature = (const float*)d_in[0];
    const float* rw1 = (const float*)d_in[1];
    const float* rb1 = (const float*)d_in[2];
    const float* rw2 = (const float*)d_in[3];
    const float* rb2 = (const float*)d_in[4];
    const float* fw1 = (const float*)d_in[5];
    const float* fb1 = (const float*)d_in[6];
    const float* fw2 = (const float*)d_in[7];
    const float* fb2 = (const float*)d_in[8];
    const float* fw3 = (const float*)d_in[9];
    const float* fb3 = (const float*)d_in[10];
    float* out = (float*)d_out;

    const int CONV1_SMEM = 62464;
    const int DYN_SMEM = 51840;
    cudaFuncSetAttribute(conv1_hmma_kernel,
                         cudaFuncAttributeMaxDynamicSharedMemorySize, CONV1_SMEM);
    cudaFuncSetAttribute(dynconv_hmma_kernel,
                         cudaFuncAttributeMaxDynamicSharedMemorySize, DYN_SMEM);

    tohwc_kernel<<<4240, 256>>>(feature, out, rw1);     // + fused wprep
    conv1_hmma_kernel<<<dim3(8, 32, 4), 256, CONV1_SMEM>>>(rb1, rw2);
    pool_fused_kernel<<<256, 256>>>(rb2);               // conv2 sum + tanh + pool

    // FC1: 64x1024 @ 1024x2048, split-K 16 (fp16 3-stage)
    gemm_hmma_kernel<<<dim3(32, 16), 256>>>(fw1, 1024, 2048, 64, 0);
    gemm_reduce_kernel<<<(64*512 + 255)/256, 256>>>(fb1, 2048, 16, 1, 0);
    // FC2: 64x2048 @ 2048x2048, split-K 16 (fp16 3-stage)
    gemm_hmma_kernel<<<dim3(32, 16), 256>>>(fw2, 2048, 2048, 128, 1);
    gemm_reduce_kernel<<<(64*512 + 255)/256, 256>>>(fb2, 2048, 16, 1, 1);
    // FC3: 64x2048 @ 2048x18464, split-K 2 (fp16 3-stage) + fused dyn W prep
    gemm_hmma_kernel<<<dim3(289, 2), 256>>>(fw3, 2048, 18464, 1024, 2);
    gemm_reduce_kernel<<<(64*4616 + 255)/256, 256>>>(fb3, 18464, 2, 0, 2);

    dynconv_hmma_kernel<<<dim3(2, 8, 64), 256, DYN_SMEM>>>(out);
}